// round 3
// baseline (speedup 1.0000x reference)
#include <cuda_runtime.h>
#include <math.h>

// Problem constants (fixed-shape instance)
#define NNODES   50000
#define NEDGES   800000
#define DIM      256
#define HDIM     128
#define NEG_SLOPE 0.2f

// ---------------------------------------------------------------------------
// Scratch (device globals; no allocation allowed)
// ---------------------------------------------------------------------------
__device__ float g_h   [NNODES * DIM];   // h = x @ W
__device__ float g_acc [NNODES * DIM];   // aggregated messages
__device__ float g_asrc[NNODES];
__device__ float g_adst[NNODES];
__device__ float g_m   [NNODES];         // segment max
__device__ float g_den [NNODES];         // segment sum of exp
__device__ float g_e   [NEDGES];         // edge logits
__device__ float g_p   [NEDGES];         // exp(e - m)
__device__ int   g_idx [2 * NEDGES];     // unpacked [src | dst] as int32
__device__ int   g_is64;                 // edge_index dtype flag

// ---------------------------------------------------------------------------
// Helpers
// ---------------------------------------------------------------------------
__device__ __forceinline__ void atomicMaxF(float* addr, float v) {
    // monotone int/uint encodings: exact float max
    if (v >= 0.0f) atomicMax((int*)addr, __float_as_int(v));
    else           atomicMin((unsigned int*)addr, __float_as_uint(v));
}

// ---------------------------------------------------------------------------
// -1) detect edge_index dtype (int32 vs int64) by value-range probing
// ---------------------------------------------------------------------------
__global__ void detect_kernel(const void* __restrict__ ei, int n_nodes) {
    const long long* p = (const long long*)ei;
    int ok64 = 1;
    #pragma unroll
    for (int i = 0; i < 8; i++) {
        long long v = p[i];
        if (v < 0 || v >= (long long)n_nodes) ok64 = 0;
    }
    g_is64 = ok64;
}

// ---------------------------------------------------------------------------
// -0.5) unpack indices to int32 (layout preserved: [src E | dst E])
// ---------------------------------------------------------------------------
__global__ void convert_kernel(const void* __restrict__ ei, int total) {
    const int i = blockIdx.x * blockDim.x + threadIdx.x;
    if (i >= total) return;
    if (g_is64) g_idx[i] = (int)((const long long*)ei)[i];
    else        g_idx[i] = ((const int*)ei)[i];
}

// ---------------------------------------------------------------------------
// 0) init: zero acc/den, m = -inf
// ---------------------------------------------------------------------------
__global__ void init_kernel(int n) {
    int i = blockIdx.x * blockDim.x + threadIdx.x;
    int total = n * DIM;
    if (i < total) g_acc[i] = 0.0f;
    if (i < n) { g_m[i] = -INFINITY; g_den[i] = 0.0f; }
}

// ---------------------------------------------------------------------------
// 1) SGEMM: C[M,Ncol] = op(A[M,K]) @ B[K,Ncol], 128x128x8 tiling, 8x8/thread
//    MODE 0: A = param ptr, C = g_h            (GEMM1: h = x @ W)
//    MODE 1: A = relu(g_acc + abias), C = relu(. + cbias) -> param ptr (GEMM2)
// ---------------------------------------------------------------------------
template<int MODE>
__global__ __launch_bounds__(256) void sgemm_kernel(
    int M, int Ncol, int K,
    const float* __restrict__ Aparam, const float* __restrict__ B,
    float* __restrict__ Cparam,
    const float* __restrict__ abias, const float* __restrict__ cbias)
{
    const int BM = 128, BN = 128, BK = 8, TM = 8, TN = 8;
    __shared__ float As[BK][BM];
    __shared__ float Bs[BK][BN];

    const float* A = (MODE == 0) ? Aparam : (const float*)g_acc;
    float*       C = (MODE == 0) ? (float*)g_h : Cparam;

    const int tid     = threadIdx.x;
    const int rowBase = blockIdx.y * BM;
    const int colBase = blockIdx.x * BN;
    const int tRow    = (tid / (BN / TN)) * TM;   // 0..120 step 8
    const int tCol    = (tid % (BN / TN)) * TN;

    // A tile loader: one float4 per thread (128 rows x 8 K)
    const int aRow = tid / (BK / 4);              // 0..127
    const int aCol = (tid % (BK / 4)) * 4;        // 0 or 4
    // B tile loader: one float4 per thread (8 rows x 128 cols)
    const int bRow = tid / (BN / 4);              // 0..7
    const int bCol = (tid % (BN / 4)) * 4;        // 0..124 step 4

    float acc[TM][TN];
    #pragma unroll
    for (int i = 0; i < TM; i++)
        #pragma unroll
        for (int j = 0; j < TN; j++) acc[i][j] = 0.0f;

    for (int k0 = 0; k0 < K; k0 += BK) {
        float4 av = make_float4(0.f, 0.f, 0.f, 0.f);
        const int gRow = rowBase + aRow;
        if (gRow < M)
            av = *reinterpret_cast<const float4*>(A + (size_t)gRow * K + k0 + aCol);
        if (MODE == 1) {
            av.x = fmaxf(av.x + abias[k0 + aCol + 0], 0.f);
            av.y = fmaxf(av.y + abias[k0 + aCol + 1], 0.f);
            av.z = fmaxf(av.z + abias[k0 + aCol + 2], 0.f);
            av.w = fmaxf(av.w + abias[k0 + aCol + 3], 0.f);
        }
        const float4 bv = *reinterpret_cast<const float4*>(
            B + (size_t)(k0 + bRow) * Ncol + colBase + bCol);

        __syncthreads();
        As[aCol + 0][aRow] = av.x;
        As[aCol + 1][aRow] = av.y;
        As[aCol + 2][aRow] = av.z;
        As[aCol + 3][aRow] = av.w;
        *reinterpret_cast<float4*>(&Bs[bRow][bCol]) = bv;
        __syncthreads();

        #pragma unroll
        for (int kk = 0; kk < BK; kk++) {
            float ra[TM], rb[TN];
            #pragma unroll
            for (int i = 0; i < TM; i++) ra[i] = As[kk][tRow + i];
            #pragma unroll
            for (int j = 0; j < TN; j++) rb[j] = Bs[kk][tCol + j];
            #pragma unroll
            for (int i = 0; i < TM; i++)
                #pragma unroll
                for (int j = 0; j < TN; j++)
                    acc[i][j] += ra[i] * rb[j];
        }
    }

    #pragma unroll
    for (int i = 0; i < TM; i++) {
        const int row = rowBase + tRow + i;
        if (row >= M) continue;
        #pragma unroll
        for (int j = 0; j < TN; j++) {
            const int col = colBase + tCol + j;
            float v = acc[i][j];
            if (MODE == 1) v = fmaxf(v + cbias[col], 0.f);
            C[(size_t)row * Ncol + col] = v;
        }
    }
}

// ---------------------------------------------------------------------------
// 2) per-node attention dots: a_src[n] = h[n].att_src ; a_dst[n] = h[n].att_dst
//    warp per node
// ---------------------------------------------------------------------------
__global__ void dots_kernel(int n,
                            const float* __restrict__ att_src,
                            const float* __restrict__ att_dst)
{
    const int warp = (blockIdx.x * blockDim.x + threadIdx.x) >> 5;
    const int lane = threadIdx.x & 31;
    if (warp >= n) return;
    const float4* hrow = reinterpret_cast<const float4*>(g_h + (size_t)warp * DIM);
    const float4* as4  = reinterpret_cast<const float4*>(att_src);
    const float4* ad4  = reinterpret_cast<const float4*>(att_dst);
    float s = 0.f, d = 0.f;
    #pragma unroll
    for (int c = lane; c < DIM / 4; c += 32) {
        const float4 hv = hrow[c];
        const float4 a  = as4[c];
        const float4 b  = ad4[c];
        s += hv.x * a.x + hv.y * a.y + hv.z * a.z + hv.w * a.w;
        d += hv.x * b.x + hv.y * b.y + hv.z * b.z + hv.w * b.w;
    }
    #pragma unroll
    for (int o = 16; o > 0; o >>= 1) {
        s += __shfl_down_sync(0xFFFFFFFFu, s, o);
        d += __shfl_down_sync(0xFFFFFFFFu, d, o);
    }
    if (lane == 0) { g_asrc[warp] = s; g_adst[warp] = d; }
}

// ---------------------------------------------------------------------------
// 3) edge pass 1: logits + leakyrelu + segment max (atomic)
// ---------------------------------------------------------------------------
__global__ void edge1_kernel(int E)
{
    const int i = blockIdx.x * blockDim.x + threadIdx.x;
    if (i >= E) return;
    const int s = g_idx[i];
    const int d = g_idx[E + i];
    float e = g_asrc[s] + g_adst[d];
    e = (e > 0.f) ? e : NEG_SLOPE * e;
    g_e[i] = e;
    atomicMaxF(&g_m[d], e);
}

// ---------------------------------------------------------------------------
// 4) edge pass 2: p = exp(e - m[dst]); denom[dst] += p
// ---------------------------------------------------------------------------
__global__ void edge2_kernel(int E)
{
    const int i = blockIdx.x * blockDim.x + threadIdx.x;
    if (i >= E) return;
    const int d = g_idx[E + i];
    const float p = expf(g_e[i] - g_m[d]);
    g_p[i] = p;
    atomicAdd(&g_den[d], p);
}

// ---------------------------------------------------------------------------
// 5) edge pass 3: acc[dst] += alpha * h[src] ; warp per edge, scalar RED adds
// ---------------------------------------------------------------------------
__global__ void edge3_kernel(int E)
{
    const int gw   = (blockIdx.x * blockDim.x + threadIdx.x) >> 5;
    const int lane = threadIdx.x & 31;
    if (gw >= E) return;

    int s = 0, d = 0;
    float alpha = 0.f;
    if (lane == 0) {
        s = g_idx[gw];
        d = g_idx[E + gw];
        alpha = g_p[gw] / (g_den[d] + 1e-16f);
    }
    s     = __shfl_sync(0xFFFFFFFFu, s, 0);
    d     = __shfl_sync(0xFFFFFFFFu, d, 0);
    alpha = __shfl_sync(0xFFFFFFFFu, alpha, 0);

    const float4* hrow = reinterpret_cast<const float4*>(g_h + (size_t)s * DIM);
    float* arow = g_acc + (size_t)d * DIM;
    #pragma unroll
    for (int c = lane; c < DIM / 4; c += 32) {
        const float4 v = hrow[c];
        atomicAdd(arow + 4 * c + 0, alpha * v.x);
        atomicAdd(arow + 4 * c + 1, alpha * v.y);
        atomicAdd(arow + 4 * c + 2, alpha * v.z);
        atomicAdd(arow + 4 * c + 3, alpha * v.w);
    }
}

// ---------------------------------------------------------------------------
// launch
// ---------------------------------------------------------------------------
extern "C" void kernel_launch(void* const* d_in, const int* in_sizes, int n_in,
                              void* d_out, int out_size)
{
    const float* x       = (const float*)d_in[0];
    const void*  ei      = d_in[1];
    const float* W       = (const float*)d_in[2];
    const float* att_src = (const float*)d_in[3];
    const float* att_dst = (const float*)d_in[4];
    const float* bias    = (const float*)d_in[5];
    const float* Wp      = (const float*)d_in[6];
    const float* bp      = (const float*)d_in[7];
    float*       out     = (float*)d_out;

    const int N = in_sizes[0] / DIM;     // 50000
    const int E = in_sizes[1] / 2;       // 800000

    // -1) detect index dtype, unpack indices to int32
    detect_kernel<<<1, 1>>>(ei, N);
    convert_kernel<<<(2 * E + 255) / 256, 256>>>(ei, 2 * E);

    // 0) init
    {
        const int total = N * DIM;
        init_kernel<<<(total + 255) / 256, 256>>>(N);
    }

    // 1) h = x @ W  (fp32 SIMT GEMM; writes g_h internally)
    {
        dim3 grid(DIM / 128, (N + 127) / 128);
        sgemm_kernel<0><<<grid, 256>>>(N, DIM, DIM, x, W, nullptr,
                                       nullptr, nullptr);
    }

    // 2) per-node dots
    dots_kernel<<<(N * 32 + 255) / 256, 256>>>(N, att_src, att_dst);

    // 3) edge logits + segment max
    edge1_kernel<<<(E + 255) / 256, 256>>>(E);

    // 4) exp + segment sum
    edge2_kernel<<<(E + 255) / 256, 256>>>(E);

    // 5) scatter-aggregate
    edge3_kernel<<<(E * 32 + 255) / 256, 256>>>(E);

    // 6) out = relu( relu(g_acc + bias) @ Wp + bp )  (reads g_acc internally)
    {
        dim3 grid(HDIM / 128, (N + 127) / 128);
        sgemm_kernel<1><<<grid, 256>>>(N, HDIM, DIM, nullptr, Wp, out,
                                       bias, bp);
    }
}

// round 6
// speedup vs baseline: 1.7009x; 1.7009x over previous
#include <cuda_runtime.h>
#include <math.h>

// Problem constants (fixed-shape instance)
#define NNODES   50000
#define NEDGES   800000
#define DIM      256
#define HDIM     128
#define NEG_SLOPE 0.2f

// ---------------------------------------------------------------------------
// Scratch (device globals; no allocation allowed)
// ---------------------------------------------------------------------------
__device__ float g_h   [NNODES * DIM];   // h = x @ W
__device__ float g_acc [NNODES * DIM];   // aggregated messages
__device__ float g_asrc[NNODES];
__device__ float g_adst[NNODES];
__device__ int   g_idx [2 * NEDGES];     // unpacked [src E | dst E] as int32
__device__ int   g_is64;                 // edge_index dtype flag
__device__ int   g_cnt [NNODES];         // per-dst degree
__device__ int   g_off [NNODES + 1];     // CSR offsets
__device__ int   g_cur [NNODES];         // scatter cursors
__device__ int   g_esrc[NEDGES];         // src node per edge, grouped by dst

// ---------------------------------------------------------------------------
// -1) detect edge_index dtype (int32 vs int64) by value-range probing
// ---------------------------------------------------------------------------
__global__ void detect_kernel(const void* __restrict__ ei, int n_nodes) {
    const long long* p = (const long long*)ei;
    int ok64 = 1;
    #pragma unroll
    for (int i = 0; i < 8; i++) {
        long long v = p[i];
        if (v < 0 || v >= (long long)n_nodes) ok64 = 0;
    }
    g_is64 = ok64;
}

// ---------------------------------------------------------------------------
// -0.5) unpack indices to int32 (layout preserved: [src E | dst E])
// ---------------------------------------------------------------------------
__global__ void convert_kernel(const void* __restrict__ ei, int total) {
    const int i = blockIdx.x * blockDim.x + threadIdx.x;
    if (i >= total) return;
    if (g_is64) g_idx[i] = (int)((const long long*)ei)[i];
    else        g_idx[i] = ((const int*)ei)[i];
}

// ---------------------------------------------------------------------------
// 0) init: zero degree counters
// ---------------------------------------------------------------------------
__global__ void init_kernel(int n) {
    int i = blockIdx.x * blockDim.x + threadIdx.x;
    if (i < n) g_cnt[i] = 0;
}

// ---------------------------------------------------------------------------
// 0.5) histogram of dst
// ---------------------------------------------------------------------------
__global__ void hist_kernel(int E) {
    const int i = blockIdx.x * blockDim.x + threadIdx.x;
    if (i >= E) return;
    atomicAdd(&g_cnt[g_idx[E + i]], 1);
}

// ---------------------------------------------------------------------------
// 0.75) single-block exclusive scan over g_cnt -> g_off, g_cur
// ---------------------------------------------------------------------------
__global__ void scan_kernel(int n) {
    __shared__ int ssum[1024];
    const int t   = threadIdx.x;
    const int SEG = (n + 1023) / 1024;
    const int base = t * SEG;

    int s = 0;
    for (int i = 0; i < SEG; i++) {
        int idx = base + i;
        if (idx < n) s += g_cnt[idx];
    }
    ssum[t] = s;
    __syncthreads();
    // Hillis-Steele inclusive scan
    for (int off = 1; off < 1024; off <<= 1) {
        int v = (t >= off) ? ssum[t - off] : 0;
        __syncthreads();
        ssum[t] += v;
        __syncthreads();
    }
    int run = (t == 0) ? 0 : ssum[t - 1];
    for (int i = 0; i < SEG; i++) {
        int idx = base + i;
        if (idx < n) {
            int c = g_cnt[idx];
            g_off[idx] = run;
            g_cur[idx] = run;
            run += c;
        }
    }
    if (t == 1023) g_off[n] = run;
}

// ---------------------------------------------------------------------------
// 0.9) scatter edges into CSR order (by dst)
// ---------------------------------------------------------------------------
__global__ void scatter_kernel(int E) {
    const int i = blockIdx.x * blockDim.x + threadIdx.x;
    if (i >= E) return;
    const int d = g_idx[E + i];
    const int pos = atomicAdd(&g_cur[d], 1);
    g_esrc[pos] = g_idx[i];
}

// ---------------------------------------------------------------------------
// 1) SGEMM: C[M,Ncol] = op(A[M,K]) @ B[K,Ncol], 128x128x8 tiling, 8x8/thread
//    MODE 0: A = param ptr, C = g_h            (GEMM1: h = x @ W)
//    MODE 1: A = relu(g_acc + abias), C = relu(. + cbias) -> param ptr (GEMM2)
// ---------------------------------------------------------------------------
template<int MODE>
__global__ __launch_bounds__(256) void sgemm_kernel(
    int M, int Ncol, int K,
    const float* __restrict__ Aparam, const float* __restrict__ B,
    float* __restrict__ Cparam,
    const float* __restrict__ abias, const float* __restrict__ cbias)
{
    const int BM = 128, BN = 128, BK = 8, TM = 8, TN = 8;
    __shared__ float As[BK][BM];
    __shared__ float Bs[BK][BN];

    const float* A = (MODE == 0) ? Aparam : (const float*)g_acc;
    float*       C = (MODE == 0) ? (float*)g_h : Cparam;

    const int tid     = threadIdx.x;
    const int rowBase = blockIdx.y * BM;
    const int colBase = blockIdx.x * BN;
    const int tRow    = (tid / (BN / TN)) * TM;
    const int tCol    = (tid % (BN / TN)) * TN;

    const int aRow = tid / (BK / 4);
    const int aCol = (tid % (BK / 4)) * 4;
    const int bRow = tid / (BN / 4);
    const int bCol = (tid % (BN / 4)) * 4;

    float acc[TM][TN];
    #pragma unroll
    for (int i = 0; i < TM; i++)
        #pragma unroll
        for (int j = 0; j < TN; j++) acc[i][j] = 0.0f;

    for (int k0 = 0; k0 < K; k0 += BK) {
        float4 av = make_float4(0.f, 0.f, 0.f, 0.f);
        const int gRow = rowBase + aRow;
        if (gRow < M)
            av = *reinterpret_cast<const float4*>(A + (size_t)gRow * K + k0 + aCol);
        if (MODE == 1) {
            av.x = fmaxf(av.x + abias[k0 + aCol + 0], 0.f);
            av.y = fmaxf(av.y + abias[k0 + aCol + 1], 0.f);
            av.z = fmaxf(av.z + abias[k0 + aCol + 2], 0.f);
            av.w = fmaxf(av.w + abias[k0 + aCol + 3], 0.f);
        }
        const float4 bv = *reinterpret_cast<const float4*>(
            B + (size_t)(k0 + bRow) * Ncol + colBase + bCol);

        __syncthreads();
        As[aCol + 0][aRow] = av.x;
        As[aCol + 1][aRow] = av.y;
        As[aCol + 2][aRow] = av.z;
        As[aCol + 3][aRow] = av.w;
        *reinterpret_cast<float4*>(&Bs[bRow][bCol]) = bv;
        __syncthreads();

        #pragma unroll
        for (int kk = 0; kk < BK; kk++) {
            float ra[TM], rb[TN];
            #pragma unroll
            for (int i = 0; i < TM; i++) ra[i] = As[kk][tRow + i];
            #pragma unroll
            for (int j = 0; j < TN; j++) rb[j] = Bs[kk][tCol + j];
            #pragma unroll
            for (int i = 0; i < TM; i++)
                #pragma unroll
                for (int j = 0; j < TN; j++)
                    acc[i][j] += ra[i] * rb[j];
        }
    }

    #pragma unroll
    for (int i = 0; i < TM; i++) {
        const int row = rowBase + tRow + i;
        if (row >= M) continue;
        #pragma unroll
        for (int j = 0; j < TN; j++) {
            const int col = colBase + tCol + j;
            float v = acc[i][j];
            if (MODE == 1) v = fmaxf(v + cbias[col], 0.f);
            C[(size_t)row * Ncol + col] = v;
        }
    }
}

// ---------------------------------------------------------------------------
// 2) per-node attention dots: a_src[n] = h[n].att_src ; a_dst[n] = h[n].att_dst
// ---------------------------------------------------------------------------
__global__ void dots_kernel(int n,
                            const float* __restrict__ att_src,
                            const float* __restrict__ att_dst)
{
    const int warp = (blockIdx.x * blockDim.x + threadIdx.x) >> 5;
    const int lane = threadIdx.x & 31;
    if (warp >= n) return;
    const float4* hrow = reinterpret_cast<const float4*>(g_h + (size_t)warp * DIM);
    const float4* as4  = reinterpret_cast<const float4*>(att_src);
    const float4* ad4  = reinterpret_cast<const float4*>(att_dst);
    float s = 0.f, d = 0.f;
    #pragma unroll
    for (int c = lane; c < DIM / 4; c += 32) {
        const float4 hv = hrow[c];
        const float4 a  = as4[c];
        const float4 b  = ad4[c];
        s += hv.x * a.x + hv.y * a.y + hv.z * a.z + hv.w * a.w;
        d += hv.x * b.x + hv.y * b.y + hv.z * b.z + hv.w * b.w;
    }
    #pragma unroll
    for (int o = 16; o > 0; o >>= 1) {
        s += __shfl_down_sync(0xFFFFFFFFu, s, o);
        d += __shfl_down_sync(0xFFFFFFFFu, d, o);
    }
    if (lane == 0) { g_asrc[warp] = s; g_adst[warp] = d; }
}

// ---------------------------------------------------------------------------
// 3) fused softmax + aggregate: warp per dst node
//    acc[d] = (sum_j exp(e_j - m) * h[src_j]) / (sum_j exp(e_j - m) + 1e-16)
// ---------------------------------------------------------------------------
__global__ __launch_bounds__(256) void agg_kernel(int N)
{
    const int warp = (blockIdx.x * blockDim.x + threadIdx.x) >> 5;
    const int lane = threadIdx.x & 31;
    if (warp >= N) return;
    const int d   = warp;
    const int beg = g_off[d];
    const int end = g_off[d + 1];
    const float adst = g_adst[d];

    // pass 1: segment max
    float m = -INFINITY;
    for (int j = beg + lane; j < end; j += 32) {
        float e = g_asrc[g_esrc[j]] + adst;
        e = (e > 0.f) ? e : NEG_SLOPE * e;
        m = fmaxf(m, e);
    }
    #pragma unroll
    for (int o = 16; o > 0; o >>= 1)
        m = fmaxf(m, __shfl_xor_sync(0xFFFFFFFFu, m, o));

    // pass 2: accumulate den and p * h[src]
    float den = 0.f;
    float4 acc0 = make_float4(0.f, 0.f, 0.f, 0.f);
    float4 acc1 = make_float4(0.f, 0.f, 0.f, 0.f);
    for (int jb = beg; jb < end; jb += 32) {
        int   s = 0;
        float p = 0.f;
        const int j = jb + lane;
        if (j < end) {
            s = g_esrc[j];
            float e = g_asrc[s] + adst;
            e = (e > 0.f) ? e : NEG_SLOPE * e;
            p = expf(e - m);
        }
        den += p;
        const int cnt = min(32, end - jb);
        for (int k = 0; k < cnt; k++) {
            const float pk = __shfl_sync(0xFFFFFFFFu, p, k);
            const int   sk = __shfl_sync(0xFFFFFFFFu, s, k);
            const float4* hr = reinterpret_cast<const float4*>(g_h + (size_t)sk * DIM);
            const float4 v0 = hr[lane];
            const float4 v1 = hr[lane + 32];
            acc0.x += pk * v0.x; acc0.y += pk * v0.y;
            acc0.z += pk * v0.z; acc0.w += pk * v0.w;
            acc1.x += pk * v1.x; acc1.y += pk * v1.y;
            acc1.z += pk * v1.z; acc1.w += pk * v1.w;
        }
    }
    #pragma unroll
    for (int o = 16; o > 0; o >>= 1)
        den += __shfl_xor_sync(0xFFFFFFFFu, den, o);
    const float inv = 1.f / (den + 1e-16f);

    float4* ar = reinterpret_cast<float4*>(g_acc + (size_t)d * DIM);
    acc0.x *= inv; acc0.y *= inv; acc0.z *= inv; acc0.w *= inv;
    acc1.x *= inv; acc1.y *= inv; acc1.z *= inv; acc1.w *= inv;
    ar[lane]      = acc0;
    ar[lane + 32] = acc1;
}

// ---------------------------------------------------------------------------
// launch
// ---------------------------------------------------------------------------
extern "C" void kernel_launch(void* const* d_in, const int* in_sizes, int n_in,
                              void* d_out, int out_size)
{
    const float* x       = (const float*)d_in[0];
    const void*  ei      = d_in[1];
    const float* W       = (const float*)d_in[2];
    const float* att_src = (const float*)d_in[3];
    const float* att_dst = (const float*)d_in[4];
    const float* bias    = (const float*)d_in[5];
    const float* Wp      = (const float*)d_in[6];
    const float* bp      = (const float*)d_in[7];
    float*       out     = (float*)d_out;

    const int N = in_sizes[0] / DIM;     // 50000
    const int E = in_sizes[1] / 2;       // 800000

    // index dtype probe + unpack
    detect_kernel<<<1, 1>>>(ei, N);
    convert_kernel<<<(2 * E + 255) / 256, 256>>>(ei, 2 * E);

    // CSR build
    init_kernel<<<(N + 255) / 256, 256>>>(N);
    hist_kernel<<<(E + 255) / 256, 256>>>(E);
    scan_kernel<<<1, 1024>>>(N);
    scatter_kernel<<<(E + 255) / 256, 256>>>(E);

    // GEMM1: h = x @ W
    {
        dim3 grid(DIM / 128, (N + 127) / 128);
        sgemm_kernel<0><<<grid, 256>>>(N, DIM, DIM, x, W, nullptr,
                                       nullptr, nullptr);
    }

    // attention dots
    dots_kernel<<<(N * 32 + 255) / 256, 256>>>(N, att_src, att_dst);

    // fused softmax + aggregate
    agg_kernel<<<(N * 32 + 255) / 256, 256>>>(N);

    // GEMM2: out = relu( relu(g_acc + bias) @ Wp + bp )
    {
        dim3 grid(HDIM / 128, (N + 127) / 128);
        sgemm_kernel<1><<<grid, 256>>>(N, HDIM, DIM, nullptr, Wp, out,
                                       bias, bp);
    }
}

// round 7
// speedup vs baseline: 2.0527x; 1.2068x over previous
#include <cuda_runtime.h>
#include <math.h>

// Problem constants (fixed-shape instance)
#define NNODES   50000
#define NEDGES   800000
#define DIM      256
#define HDIM     128
#define NEG_SLOPE 0.2f

// ---------------------------------------------------------------------------
// Scratch (device globals; no allocation allowed)
// ---------------------------------------------------------------------------
__device__ float g_h   [NNODES * DIM];   // h = x @ W
__device__ float g_acc [NNODES * DIM];   // aggregated messages
__device__ float g_asrc[NNODES];
__device__ float g_adst[NNODES];
__device__ int   g_idx [2 * NEDGES];     // unpacked [src E | dst E] as int32
__device__ int   g_is64;                 // edge_index dtype flag
__device__ int   g_cnt [NNODES];         // per-dst degree
__device__ int   g_off [NNODES + 1];     // CSR offsets
__device__ int   g_cur [NNODES];         // scatter cursors
__device__ int   g_esrc[NEDGES];         // src node per edge, grouped by dst

// ---------------------------------------------------------------------------
// Helpers
// ---------------------------------------------------------------------------
__device__ __forceinline__ unsigned f2tf32(float f) {
    unsigned r;
    asm("cvt.rna.tf32.f32 %0, %1;" : "=r"(r) : "f"(f));
    return r;
}

__device__ __forceinline__ void mma_tf32(float d[4], unsigned a0, unsigned a1,
                                         unsigned a2, unsigned a3,
                                         unsigned b0, unsigned b1) {
    asm volatile(
        "mma.sync.aligned.m16n8k8.row.col.f32.tf32.tf32.f32 "
        "{%0,%1,%2,%3},{%4,%5,%6,%7},{%8,%9},{%0,%1,%2,%3};"
        : "+f"(d[0]), "+f"(d[1]), "+f"(d[2]), "+f"(d[3])
        : "r"(a0), "r"(a1), "r"(a2), "r"(a3), "r"(b0), "r"(b1));
}

// ---------------------------------------------------------------------------
// -1) detect edge_index dtype (int32 vs int64) by value-range probing
// ---------------------------------------------------------------------------
__global__ void detect_kernel(const void* __restrict__ ei, int n_nodes) {
    const long long* p = (const long long*)ei;
    int ok64 = 1;
    #pragma unroll
    for (int i = 0; i < 8; i++) {
        long long v = p[i];
        if (v < 0 || v >= (long long)n_nodes) ok64 = 0;
    }
    g_is64 = ok64;
}

// ---------------------------------------------------------------------------
// -0.5) unpack indices to int32 (layout preserved: [src E | dst E])
// ---------------------------------------------------------------------------
__global__ void convert_kernel(const void* __restrict__ ei, int total) {
    const int i = blockIdx.x * blockDim.x + threadIdx.x;
    if (i >= total) return;
    if (g_is64) g_idx[i] = (int)((const long long*)ei)[i];
    else        g_idx[i] = ((const int*)ei)[i];
}

// ---------------------------------------------------------------------------
// 0) init: zero degree counters
// ---------------------------------------------------------------------------
__global__ void init_kernel(int n) {
    int i = blockIdx.x * blockDim.x + threadIdx.x;
    if (i < n) g_cnt[i] = 0;
}

// ---------------------------------------------------------------------------
// 0.5) histogram of dst
// ---------------------------------------------------------------------------
__global__ void hist_kernel(int E) {
    const int i = blockIdx.x * blockDim.x + threadIdx.x;
    if (i >= E) return;
    atomicAdd(&g_cnt[g_idx[E + i]], 1);
}

// ---------------------------------------------------------------------------
// 0.75) single-block exclusive scan over g_cnt -> g_off, g_cur
// ---------------------------------------------------------------------------
__global__ void scan_kernel(int n) {
    __shared__ int ssum[1024];
    const int t   = threadIdx.x;
    const int SEG = (n + 1023) / 1024;
    const int base = t * SEG;

    int s = 0;
    for (int i = 0; i < SEG; i++) {
        int idx = base + i;
        if (idx < n) s += g_cnt[idx];
    }
    ssum[t] = s;
    __syncthreads();
    for (int off = 1; off < 1024; off <<= 1) {
        int v = (t >= off) ? ssum[t - off] : 0;
        __syncthreads();
        ssum[t] += v;
        __syncthreads();
    }
    int run = (t == 0) ? 0 : ssum[t - 1];
    for (int i = 0; i < SEG; i++) {
        int idx = base + i;
        if (idx < n) {
            int c = g_cnt[idx];
            g_off[idx] = run;
            g_cur[idx] = run;
            run += c;
        }
    }
    if (t == 1023) g_off[n] = run;
}

// ---------------------------------------------------------------------------
// 0.9) scatter edges into CSR order (by dst)
// ---------------------------------------------------------------------------
__global__ void scatter_kernel(int E) {
    const int i = blockIdx.x * blockDim.x + threadIdx.x;
    if (i >= E) return;
    const int d = g_idx[E + i];
    const int pos = atomicAdd(&g_cur[d], 1);
    g_esrc[pos] = g_idx[i];
}

// ---------------------------------------------------------------------------
// 1) Tensor-core GEMM (tf32 mma.m16n8k8, 3-term split for fp32 accuracy)
//    C[M,Ncol] = op(A[M,K]) @ B[K,Ncol]
//    Block tile 128x128x16, 8 warps, warp tile 32x64.
//    MODE 0: A = param ptr (x), C = g_h
//    MODE 1: A = relu(g_acc + abias), C = relu(. + cbias) -> param ptr
// ---------------------------------------------------------------------------
template<int MODE>
__global__ __launch_bounds__(256) void mma_gemm_kernel(
    int M, int Ncol, int K,
    const float* __restrict__ Aparam, const float* __restrict__ B,
    float* __restrict__ Cparam,
    const float* __restrict__ abias, const float* __restrict__ cbias)
{
    const int BM = 128, BN = 128, BK = 16;
    __shared__ float As[BM][BK + 1];     // [row][k]
    __shared__ float Bs[BK][BN + 4];     // [k][col]

    const float* A = (MODE == 0) ? Aparam : (const float*)g_acc;
    float*       C = (MODE == 0) ? (float*)g_h : Cparam;

    const int tid     = threadIdx.x;
    const int lane    = tid & 31;
    const int warp    = tid >> 5;
    const int warpM   = warp & 3;        // 0..3  (32-row slabs)
    const int warpN   = warp >> 2;       // 0..1  (64-col slabs)
    const int rowBase = blockIdx.y * BM;
    const int colBase = blockIdx.x * BN;

    const int r = lane >> 2;             // 0..7
    const int c = lane & 3;              // 0..3

    // global->smem loaders: A tile 128x16 (512 float4), B tile 16x128 (512 float4)
    // each thread does 2 float4 for each
    float acc[2][8][4];
    #pragma unroll
    for (int mt = 0; mt < 2; mt++)
        #pragma unroll
        for (int nt = 0; nt < 8; nt++)
            #pragma unroll
            for (int j = 0; j < 4; j++) acc[mt][nt][j] = 0.f;

    for (int k0 = 0; k0 < K; k0 += BK) {
        // ---- load A tile ----
        #pragma unroll
        for (int t = 0; t < 2; t++) {
            const int idx  = tid + t * 256;        // 0..511
            const int row  = idx >> 2;             // 0..127
            const int col4 = (idx & 3) * 4;        // 0,4,8,12
            float4 av = make_float4(0.f, 0.f, 0.f, 0.f);
            const int gRow = rowBase + row;
            if (gRow < M)
                av = *reinterpret_cast<const float4*>(A + (size_t)gRow * K + k0 + col4);
            if (MODE == 1) {
                av.x = fmaxf(av.x + abias[k0 + col4 + 0], 0.f);
                av.y = fmaxf(av.y + abias[k0 + col4 + 1], 0.f);
                av.z = fmaxf(av.z + abias[k0 + col4 + 2], 0.f);
                av.w = fmaxf(av.w + abias[k0 + col4 + 3], 0.f);
            }
            As[row][col4 + 0] = av.x;
            As[row][col4 + 1] = av.y;
            As[row][col4 + 2] = av.z;
            As[row][col4 + 3] = av.w;
        }
        // ---- load B tile ----
        #pragma unroll
        for (int t = 0; t < 2; t++) {
            const int idx  = tid + t * 256;        // 0..511
            const int row  = idx >> 5;             // 0..15
            const int col4 = (idx & 31) * 4;       // 0..124
            const float4 bv = *reinterpret_cast<const float4*>(
                B + (size_t)(k0 + row) * Ncol + colBase + col4);
            Bs[row][col4 + 0] = bv.x;
            Bs[row][col4 + 1] = bv.y;
            Bs[row][col4 + 2] = bv.z;
            Bs[row][col4 + 3] = bv.w;
        }
        __syncthreads();

        #pragma unroll
        for (int kk = 0; kk < BK; kk += 8) {
            // A fragments (2 m-subtiles), split hi/lo
            unsigned ahi[2][4], alo[2][4];
            #pragma unroll
            for (int mt = 0; mt < 2; mt++) {
                const int ar = warpM * 32 + mt * 16 + r;
                float a0 = As[ar][kk + c];
                float a1 = As[ar + 8][kk + c];
                float a2 = As[ar][kk + c + 4];
                float a3 = As[ar + 8][kk + c + 4];
                ahi[mt][0] = f2tf32(a0); alo[mt][0] = f2tf32(a0 - __uint_as_float(ahi[mt][0]));
                ahi[mt][1] = f2tf32(a1); alo[mt][1] = f2tf32(a1 - __uint_as_float(ahi[mt][1]));
                ahi[mt][2] = f2tf32(a2); alo[mt][2] = f2tf32(a2 - __uint_as_float(ahi[mt][2]));
                ahi[mt][3] = f2tf32(a3); alo[mt][3] = f2tf32(a3 - __uint_as_float(ahi[mt][3]));
            }
            // B fragments (8 n-subtiles), split hi/lo
            unsigned bhi[8][2], blo[8][2];
            #pragma unroll
            for (int nt = 0; nt < 8; nt++) {
                const int bc = warpN * 64 + nt * 8 + r;
                float b0 = Bs[kk + c][bc];
                float b1 = Bs[kk + c + 4][bc];
                bhi[nt][0] = f2tf32(b0); blo[nt][0] = f2tf32(b0 - __uint_as_float(bhi[nt][0]));
                bhi[nt][1] = f2tf32(b1); blo[nt][1] = f2tf32(b1 - __uint_as_float(bhi[nt][1]));
            }
            #pragma unroll
            for (int mt = 0; mt < 2; mt++)
                #pragma unroll
                for (int nt = 0; nt < 8; nt++) {
                    mma_tf32(acc[mt][nt], ahi[mt][0], ahi[mt][1], ahi[mt][2], ahi[mt][3],
                             bhi[nt][0], bhi[nt][1]);
                    mma_tf32(acc[mt][nt], ahi[mt][0], ahi[mt][1], ahi[mt][2], ahi[mt][3],
                             blo[nt][0], blo[nt][1]);
                    mma_tf32(acc[mt][nt], alo[mt][0], alo[mt][1], alo[mt][2], alo[mt][3],
                             bhi[nt][0], bhi[nt][1]);
                }
        }
        __syncthreads();
    }

    // ---- store C ----
    #pragma unroll
    for (int mt = 0; mt < 2; mt++) {
        #pragma unroll
        for (int nt = 0; nt < 8; nt++) {
            const int col = colBase + warpN * 64 + nt * 8 + c * 2;
            #pragma unroll
            for (int rr = 0; rr < 2; rr++) {
                const int row = rowBase + warpM * 32 + mt * 16 + r + rr * 8;
                if (row >= M) continue;
                float v0 = acc[mt][nt][rr * 2 + 0];
                float v1 = acc[mt][nt][rr * 2 + 1];
                if (MODE == 1) {
                    v0 = fmaxf(v0 + cbias[col + 0], 0.f);
                    v1 = fmaxf(v1 + cbias[col + 1], 0.f);
                }
                C[(size_t)row * Ncol + col + 0] = v0;
                C[(size_t)row * Ncol + col + 1] = v1;
            }
        }
    }
}

// ---------------------------------------------------------------------------
// 2) per-node attention dots: a_src[n] = h[n].att_src ; a_dst[n] = h[n].att_dst
// ---------------------------------------------------------------------------
__global__ void dots_kernel(int n,
                            const float* __restrict__ att_src,
                            const float* __restrict__ att_dst)
{
    const int warp = (blockIdx.x * blockDim.x + threadIdx.x) >> 5;
    const int lane = threadIdx.x & 31;
    if (warp >= n) return;
    const float4* hrow = reinterpret_cast<const float4*>(g_h + (size_t)warp * DIM);
    const float4* as4  = reinterpret_cast<const float4*>(att_src);
    const float4* ad4  = reinterpret_cast<const float4*>(att_dst);
    float s = 0.f, d = 0.f;
    #pragma unroll
    for (int c = lane; c < DIM / 4; c += 32) {
        const float4 hv = hrow[c];
        const float4 a  = as4[c];
        const float4 b  = ad4[c];
        s += hv.x * a.x + hv.y * a.y + hv.z * a.z + hv.w * a.w;
        d += hv.x * b.x + hv.y * b.y + hv.z * b.z + hv.w * b.w;
    }
    #pragma unroll
    for (int o = 16; o > 0; o >>= 1) {
        s += __shfl_down_sync(0xFFFFFFFFu, s, o);
        d += __shfl_down_sync(0xFFFFFFFFu, d, o);
    }
    if (lane == 0) { g_asrc[warp] = s; g_adst[warp] = d; }
}

// ---------------------------------------------------------------------------
// 3) fused softmax + aggregate: warp per dst node
// ---------------------------------------------------------------------------
__global__ __launch_bounds__(256) void agg_kernel(int N)
{
    const int warp = (blockIdx.x * blockDim.x + threadIdx.x) >> 5;
    const int lane = threadIdx.x & 31;
    if (warp >= N) return;
    const int d   = warp;
    const int beg = g_off[d];
    const int end = g_off[d + 1];
    const float adst = g_adst[d];

    float m = -INFINITY;
    for (int j = beg + lane; j < end; j += 32) {
        float e = g_asrc[g_esrc[j]] + adst;
        e = (e > 0.f) ? e : NEG_SLOPE * e;
        m = fmaxf(m, e);
    }
    #pragma unroll
    for (int o = 16; o > 0; o >>= 1)
        m = fmaxf(m, __shfl_xor_sync(0xFFFFFFFFu, m, o));

    float den = 0.f;
    float4 acc0 = make_float4(0.f, 0.f, 0.f, 0.f);
    float4 acc1 = make_float4(0.f, 0.f, 0.f, 0.f);
    for (int jb = beg; jb < end; jb += 32) {
        int   s = 0;
        float p = 0.f;
        const int j = jb + lane;
        if (j < end) {
            s = g_esrc[j];
            float e = g_asrc[s] + adst;
            e = (e > 0.f) ? e : NEG_SLOPE * e;
            p = expf(e - m);
        }
        den += p;
        const int cnt = min(32, end - jb);
        for (int k = 0; k < cnt; k++) {
            const float pk = __shfl_sync(0xFFFFFFFFu, p, k);
            const int   sk = __shfl_sync(0xFFFFFFFFu, s, k);
            const float4* hr = reinterpret_cast<const float4*>(g_h + (size_t)sk * DIM);
            const float4 v0 = hr[lane];
            const float4 v1 = hr[lane + 32];
            acc0.x += pk * v0.x; acc0.y += pk * v0.y;
            acc0.z += pk * v0.z; acc0.w += pk * v0.w;
            acc1.x += pk * v1.x; acc1.y += pk * v1.y;
            acc1.z += pk * v1.z; acc1.w += pk * v1.w;
        }
    }
    #pragma unroll
    for (int o = 16; o > 0; o >>= 1)
        den += __shfl_xor_sync(0xFFFFFFFFu, den, o);
    const float inv = 1.f / (den + 1e-16f);

    float4* ar = reinterpret_cast<float4*>(g_acc + (size_t)d * DIM);
    acc0.x *= inv; acc0.y *= inv; acc0.z *= inv; acc0.w *= inv;
    acc1.x *= inv; acc1.y *= inv; acc1.z *= inv; acc1.w *= inv;
    ar[lane]      = acc0;
    ar[lane + 32] = acc1;
}

// ---------------------------------------------------------------------------
// launch
// ---------------------------------------------------------------------------
extern "C" void kernel_launch(void* const* d_in, const int* in_sizes, int n_in,
                              void* d_out, int out_size)
{
    const float* x       = (const float*)d_in[0];
    const void*  ei      = d_in[1];
    const float* W       = (const float*)d_in[2];
    const float* att_src = (const float*)d_in[3];
    const float* att_dst = (const float*)d_in[4];
    const float* bias    = (const float*)d_in[5];
    const float* Wp      = (const float*)d_in[6];
    const float* bp      = (const float*)d_in[7];
    float*       out     = (float*)d_out;

    const int N = in_sizes[0] / DIM;     // 50000
    const int E = in_sizes[1] / 2;       // 800000

    // index dtype probe + unpack
    detect_kernel<<<1, 1>>>(ei, N);
    convert_kernel<<<(2 * E + 255) / 256, 256>>>(ei, 2 * E);

    // CSR build
    init_kernel<<<(N + 255) / 256, 256>>>(N);
    hist_kernel<<<(E + 255) / 256, 256>>>(E);
    scan_kernel<<<1, 1024>>>(N);
    scatter_kernel<<<(E + 255) / 256, 256>>>(E);

    // GEMM1: h = x @ W   (tensor cores, tf32 split)
    {
        dim3 grid(DIM / 128, (N + 127) / 128);
        mma_gemm_kernel<0><<<grid, 256>>>(N, DIM, DIM, x, W, nullptr,
                                          nullptr, nullptr);
    }

    // attention dots
    dots_kernel<<<(N * 32 + 255) / 256, 256>>>(N, att_src, att_dst);

    // fused softmax + aggregate
    agg_kernel<<<(N * 32 + 255) / 256, 256>>>(N);

    // GEMM2: out = relu( relu(g_acc + bias) @ Wp + bp )
    {
        dim3 grid(HDIM / 128, (N + 127) / 128);
        mma_gemm_kernel<1><<<grid, 256>>>(N, HDIM, DIM, nullptr, Wp, out,
                                          bias, bp);
    }
}